// round 1
// baseline (speedup 1.0000x reference)
#include <cuda_runtime.h>

#define D_MODEL 256
#define N_HEADS 8
#define HEAD_DIM 32
#define N_TOTAL 24576
#define BATCH 64
#define SEQ 512
#define NP (BATCH * SEQ)  // 32768 packed tokens

// Scratch (device globals — allocation-free rule)
__device__ float g_Q[NP * D_MODEL];
__device__ float g_K[NP * D_MODEL];
__device__ float g_V[NP * D_MODEL];
__device__ float g_Y[NP * D_MODEL];

// ---------------------------------------------------------------------------
// Kernel 1: gather + QKV projection.
// out[p][c] = sum_k x[idx[p]][k] * W[c][k] + bias[c], stored [B,H,T,D].
// Tile 64 tokens x 64 channels, K staged in 32-chunks, 4x4 micro-tile/thread.
// grid: (NP/64, 4, 3)  block: 256
// ---------------------------------------------------------------------------
__global__ __launch_bounds__(256)
void qkv_kernel(const float* __restrict__ x,
                const int* __restrict__ idx,
                const float* __restrict__ Wq, const float* __restrict__ bq,
                const float* __restrict__ Wk, const float* __restrict__ bk,
                const float* __restrict__ Wv, const float* __restrict__ bv)
{
    __shared__ float As[64][33];
    __shared__ float Bs[64][33];
    __shared__ int   rowIdx[64];

    const int mat = blockIdx.z;
    const float* __restrict__ W    = (mat == 0) ? Wq : (mat == 1) ? Wk : Wv;
    const float* __restrict__ bias = (mat == 0) ? bq : (mat == 1) ? bk : bv;
    float* __restrict__ Out        = (mat == 0) ? g_Q : (mat == 1) ? g_K : g_V;

    const int tok0 = blockIdx.x * 64;
    const int n0   = blockIdx.y * 64;
    const int tid  = threadIdx.x;
    const int tx = tid & 15, ty = tid >> 4;

    if (tid < 64) rowIdx[tid] = idx[tok0 + tid];
    __syncthreads();

    float acc[4][4] = {};

    for (int kk = 0; kk < D_MODEL; kk += 32) {
#pragma unroll
        for (int i = 0; i < 8; i++) {
            int e = tid + i * 256;            // 0..2047
            int r = e >> 5, c = e & 31;
            As[r][c] = x[rowIdx[r] * D_MODEL + kk + c];
            Bs[r][c] = W[(n0 + r) * D_MODEL + kk + c];
        }
        __syncthreads();
#pragma unroll
        for (int k = 0; k < 32; k++) {
            float a[4], b[4];
#pragma unroll
            for (int i = 0; i < 4; i++) a[i] = As[ty * 4 + i][k];
#pragma unroll
            for (int j = 0; j < 4; j++) b[j] = Bs[tx * 4 + j][k];
#pragma unroll
            for (int i = 0; i < 4; i++)
#pragma unroll
                for (int j = 0; j < 4; j++) acc[i][j] += a[i] * b[j];
        }
        __syncthreads();
    }

#pragma unroll
    for (int i = 0; i < 4; i++) {
        int p = tok0 + ty * 4 + i;
        int b = p >> 9, t = p & 511;
#pragma unroll
        for (int j = 0; j < 4; j++) {
            int c = n0 + tx * 4 + j;
            int h = c >> 5, d = c & 31;
            Out[((b * N_HEADS + h) * SEQ + t) * HEAD_DIM + d] = acc[i][j] + bias[c];
        }
    }
}

// ---------------------------------------------------------------------------
// Kernel 2: fused masked attention per (b, h, 64-query tile), online softmax.
// Mask: score = -1e9 where pb[b][i] == pb[b][j]  (matches reference).
// grid: (SEQ/64, N_HEADS, BATCH)  block: 256
// ---------------------------------------------------------------------------
__global__ __launch_bounds__(256)
void attn_kernel(const int* __restrict__ pb)
{
    __shared__ float Qs[64][33];
    __shared__ float Ks[64][33];
    __shared__ float Vs[64][33];
    __shared__ float Ss[64][65];
    __shared__ float m_s[64], l_s[64], alpha_s[64];
    __shared__ int   pbq[64], pbk[64];

    const int b  = blockIdx.z;
    const int h  = blockIdx.y;
    const int q0 = blockIdx.x * 64;
    const int tid = threadIdx.x;
    const int tx = tid & 15, ty = tid >> 4;
    const float scale = 0.17677669529663687f; // 1/sqrt(32)

    const float* __restrict__ Qg = g_Q + (b * N_HEADS + h) * SEQ * HEAD_DIM;
    const float* __restrict__ Kg = g_K + (b * N_HEADS + h) * SEQ * HEAD_DIM;
    const float* __restrict__ Vg = g_V + (b * N_HEADS + h) * SEQ * HEAD_DIM;

#pragma unroll
    for (int i = 0; i < 8; i++) {
        int e = tid + i * 256;
        int r = e >> 5, c = e & 31;
        Qs[r][c] = Qg[(q0 + r) * HEAD_DIM + c];
    }
    if (tid < 64) {
        pbq[tid] = pb[b * SEQ + q0 + tid];
        m_s[tid] = -1e30f;
        l_s[tid] = 0.f;
    }

    // output accumulators: rows ty*4+i, dims tx*2+{0,1}
    float o[4][2] = {};

    for (int k0 = 0; k0 < SEQ; k0 += 64) {
        __syncthreads();  // also orders Qs/pbq on first iter, protects Ks/Vs reuse
#pragma unroll
        for (int i = 0; i < 8; i++) {
            int e = tid + i * 256;
            int r = e >> 5, c = e & 31;
            Ks[r][c] = Kg[(k0 + r) * HEAD_DIM + c];
            Vs[r][c] = Vg[(k0 + r) * HEAD_DIM + c];
        }
        if (tid < 64) pbk[tid] = pb[b * SEQ + k0 + tid];
        __syncthreads();

        // S = Q K^T  (4x4 micro per thread)
        float s[4][4] = {};
#pragma unroll
        for (int k = 0; k < 32; k++) {
            float a[4], c4[4];
#pragma unroll
            for (int i = 0; i < 4; i++) a[i]  = Qs[ty * 4 + i][k];
#pragma unroll
            for (int j = 0; j < 4; j++) c4[j] = Ks[tx * 4 + j][k];
#pragma unroll
            for (int i = 0; i < 4; i++)
#pragma unroll
                for (int j = 0; j < 4; j++) s[i][j] += a[i] * c4[j];
        }
#pragma unroll
        for (int i = 0; i < 4; i++) {
            int r = ty * 4 + i;
#pragma unroll
            for (int j = 0; j < 4; j++) {
                int c = tx * 4 + j;
                Ss[r][c] = (pbq[r] == pbk[c]) ? -1e9f : s[i][j] * scale;
            }
        }
        __syncthreads();

        // online softmax row update (one row per thread, 64 threads)
        if (tid < 64) {
            float mold = m_s[tid];
            float mnew = mold;
#pragma unroll 8
            for (int j = 0; j < 64; j++) mnew = fmaxf(mnew, Ss[tid][j]);
            float al = __expf(mold - mnew);
            float lsum = 0.f;
#pragma unroll 8
            for (int j = 0; j < 64; j++) {
                float p = __expf(Ss[tid][j] - mnew);
                Ss[tid][j] = p;
                lsum += p;
            }
            m_s[tid] = mnew;
            l_s[tid] = l_s[tid] * al + lsum;
            alpha_s[tid] = al;
        }
        __syncthreads();

        // rescale accumulators and accumulate P * V
#pragma unroll
        for (int i = 0; i < 4; i++) {
            float al = alpha_s[ty * 4 + i];
            o[i][0] *= al;
            o[i][1] *= al;
        }
#pragma unroll 4
        for (int j = 0; j < 64; j++) {
            float v0 = Vs[j][tx * 2 + 0];
            float v1 = Vs[j][tx * 2 + 1];
#pragma unroll
            for (int i = 0; i < 4; i++) {
                float p = Ss[ty * 4 + i][j];
                o[i][0] += p * v0;
                o[i][1] += p * v1;
            }
        }
    }
    __syncthreads();

    // write y in [token][channel] layout for the output projection
#pragma unroll
    for (int i = 0; i < 4; i++) {
        int r = ty * 4 + i;
        float inv = 1.f / l_s[r];
        int p = b * SEQ + q0 + r;
        int c = h * HEAD_DIM + tx * 2;
        g_Y[p * D_MODEL + c + 0] = o[i][0] * inv;
        g_Y[p * D_MODEL + c + 1] = o[i][1] * inv;
    }
}

// ---------------------------------------------------------------------------
// Kernel 3: output projection fused with inverse-index gather.
// out[n][c] = sum_k Y[inv[n]][k] * Wp[c][k] + bp[c]
// grid: (N_TOTAL/64, 4)  block: 256
// ---------------------------------------------------------------------------
__global__ __launch_bounds__(256)
void proj_kernel(const float* __restrict__ Wp, const float* __restrict__ bp,
                 const int* __restrict__ inv, float* __restrict__ out)
{
    __shared__ float As[64][33];
    __shared__ float Bs[64][33];
    __shared__ int   rowIdx[64];

    const int n_row0 = blockIdx.x * 64;
    const int n0     = blockIdx.y * 64;
    const int tid = threadIdx.x;
    const int tx = tid & 15, ty = tid >> 4;

    if (tid < 64) rowIdx[tid] = inv[n_row0 + tid];
    __syncthreads();

    float acc[4][4] = {};

    for (int kk = 0; kk < D_MODEL; kk += 32) {
#pragma unroll
        for (int i = 0; i < 8; i++) {
            int e = tid + i * 256;
            int r = e >> 5, c = e & 31;
            As[r][c] = g_Y[rowIdx[r] * D_MODEL + kk + c];
            Bs[r][c] = Wp[(n0 + r) * D_MODEL + kk + c];
        }
        __syncthreads();
#pragma unroll
        for (int k = 0; k < 32; k++) {
            float a[4], b[4];
#pragma unroll
            for (int i = 0; i < 4; i++) a[i] = As[ty * 4 + i][k];
#pragma unroll
            for (int j = 0; j < 4; j++) b[j] = Bs[tx * 4 + j][k];
#pragma unroll
            for (int i = 0; i < 4; i++)
#pragma unroll
                for (int j = 0; j < 4; j++) acc[i][j] += a[i] * b[j];
        }
        __syncthreads();
    }

#pragma unroll
    for (int i = 0; i < 4; i++) {
        int n = n_row0 + ty * 4 + i;
#pragma unroll
        for (int j = 0; j < 4; j++) {
            int c = n0 + tx * 4 + j;
            out[n * D_MODEL + c] = acc[i][j] + bp[c];
        }
    }
}

// ---------------------------------------------------------------------------
extern "C" void kernel_launch(void* const* d_in, const int* in_sizes, int n_in,
                              void* d_out, int out_size)
{
    const float* x  = (const float*)d_in[0];
    const float* Wq = (const float*)d_in[1];
    const float* bq = (const float*)d_in[2];
    const float* Wk = (const float*)d_in[3];
    const float* bk = (const float*)d_in[4];
    const float* Wv = (const float*)d_in[5];
    const float* bv = (const float*)d_in[6];
    const float* Wp = (const float*)d_in[7];
    const float* bp = (const float*)d_in[8];
    const int* idx  = (const int*)d_in[9];
    const int* pb   = (const int*)d_in[10];
    const int* inv  = (const int*)d_in[11];
    float* out = (float*)d_out;

    dim3 g1(NP / 64, 4, 3);
    qkv_kernel<<<g1, 256>>>(x, idx, Wq, bq, Wk, bk, Wv, bv);

    dim3 g2(SEQ / 64, N_HEADS, BATCH);
    attn_kernel<<<g2, 256>>>(pb);

    dim3 g3(N_TOTAL / 64, 4);
    proj_kernel<<<g3, 256>>>(Wp, bp, inv, out);
}

// round 3
// speedup vs baseline: 3.3954x; 3.3954x over previous
#include <cuda_runtime.h>
#include <cstdint>

#define D_MODEL 256
#define N_HEADS 8
#define HEAD_DIM 32
#define N_TOTAL 24576
#define BATCH 64
#define SEQ 512
#define NP (BATCH * SEQ)  // 32768 packed tokens

// Scratch (device globals — allocation-free rule)
__device__ float g_Q[NP * D_MODEL];
__device__ float g_K[NP * D_MODEL];
__device__ float g_V[NP * D_MODEL];
__device__ float g_Y[NP * D_MODEL];

// ---------------------------------------------------------------------------
// helpers
// ---------------------------------------------------------------------------
__device__ __forceinline__ uint32_t f2tf32(float f) {
    uint32_t u;
    asm("cvt.rna.tf32.f32 %0, %1;" : "=r"(u) : "f"(f));
    return u;
}

__device__ __forceinline__ void mma_tf32(float& d0, float& d1, float& d2, float& d3,
                                         uint32_t a0, uint32_t a1, uint32_t a2, uint32_t a3,
                                         uint32_t b0, uint32_t b1) {
    asm volatile(
        "mma.sync.aligned.m16n8k8.row.col.f32.tf32.tf32.f32 "
        "{%0,%1,%2,%3}, {%4,%5,%6,%7}, {%8,%9}, {%0,%1,%2,%3};"
        : "+f"(d0), "+f"(d1), "+f"(d2), "+f"(d3)
        : "r"(a0), "r"(a1), "r"(a2), "r"(a3), "r"(b0), "r"(b1));
}

// ---------------------------------------------------------------------------
// Kernel 1: gather + QKV projection via tf32 MMA.
// out[p][c] = sum_k x[idx[p]][k] * W[c][k] + bias[c], stored [B,H,T,D].
// Block tile 128(M) x 64(N), K chunks of 32. 8 warps: 4(M) x 2(N), warp 32x32.
// grid: (NP/128, 4, 3)  block: 256
// ---------------------------------------------------------------------------
__global__ __launch_bounds__(256)
void qkv_kernel(const float* __restrict__ x,
                const int* __restrict__ idx,
                const float* __restrict__ Wq, const float* __restrict__ bq,
                const float* __restrict__ Wk, const float* __restrict__ bk,
                const float* __restrict__ Wv, const float* __restrict__ bv)
{
    __shared__ uint32_t As[128][36];
    __shared__ uint32_t Bs[64][36];
    __shared__ int rowIdx[128];

    const int mat = blockIdx.z;
    const float* __restrict__ W    = (mat == 0) ? Wq : (mat == 1) ? Wk : Wv;
    const float* __restrict__ bias = (mat == 0) ? bq : (mat == 1) ? bk : bv;
    float* __restrict__ Out        = (mat == 0) ? g_Q : (mat == 1) ? g_K : g_V;

    const int tok0 = blockIdx.x * 128;
    const int n0   = blockIdx.y * 64;
    const int tid  = threadIdx.x;
    const int warp = tid >> 5, lane = tid & 31;
    const int wm = warp >> 1, wn = warp & 1;
    const int group = lane >> 2, tig = lane & 3;

    if (tid < 128) rowIdx[tid] = idx[tok0 + tid];
    __syncthreads();

    float acc[2][4][4] = {};

    for (int kk = 0; kk < D_MODEL; kk += 32) {
        // stage A: 128x32 gathered rows of x
#pragma unroll
        for (int i = 0; i < 4; i++) {
            int quad = tid + 256 * i;       // 0..1023
            int r = quad >> 3, c = (quad & 7) * 4;
            const float4 v = *(const float4*)(x + rowIdx[r] * D_MODEL + kk + c);
            As[r][c + 0] = f2tf32(v.x);
            As[r][c + 1] = f2tf32(v.y);
            As[r][c + 2] = f2tf32(v.z);
            As[r][c + 3] = f2tf32(v.w);
        }
        // stage B: 64x32 of W (row-major [N][K])
#pragma unroll
        for (int i = 0; i < 2; i++) {
            int quad = tid + 256 * i;       // 0..511
            int r = quad >> 3, c = (quad & 7) * 4;
            const float4 v = *(const float4*)(W + (n0 + r) * D_MODEL + kk + c);
            Bs[r][c + 0] = f2tf32(v.x);
            Bs[r][c + 1] = f2tf32(v.y);
            Bs[r][c + 2] = f2tf32(v.z);
            Bs[r][c + 3] = f2tf32(v.w);
        }
        __syncthreads();

#pragma unroll
        for (int ks = 0; ks < 4; ks++) {
            uint32_t afr[2][4];
#pragma unroll
            for (int mt = 0; mt < 2; mt++) {
                int r = wm * 32 + mt * 16 + group;
                afr[mt][0] = As[r][ks * 8 + tig];
                afr[mt][1] = As[r + 8][ks * 8 + tig];
                afr[mt][2] = As[r][ks * 8 + tig + 4];
                afr[mt][3] = As[r + 8][ks * 8 + tig + 4];
            }
#pragma unroll
            for (int nt = 0; nt < 4; nt++) {
                int n = wn * 32 + nt * 8 + group;
                uint32_t b0 = Bs[n][ks * 8 + tig];
                uint32_t b1 = Bs[n][ks * 8 + tig + 4];
#pragma unroll
                for (int mt = 0; mt < 2; mt++)
                    mma_tf32(acc[mt][nt][0], acc[mt][nt][1], acc[mt][nt][2], acc[mt][nt][3],
                             afr[mt][0], afr[mt][1], afr[mt][2], afr[mt][3], b0, b1);
            }
        }
        __syncthreads();
    }

    // epilogue: add bias, write [B,H,T,D]
#pragma unroll
    for (int mt = 0; mt < 2; mt++) {
#pragma unroll
        for (int nt = 0; nt < 4; nt++) {
            int c = n0 + wn * 32 + nt * 8 + 2 * tig;
            int h = c >> 5, d = c & 31;
            float b0 = bias[c], b1 = bias[c + 1];
#pragma unroll
            for (int rr = 0; rr < 2; rr++) {
                int p = tok0 + wm * 32 + mt * 16 + group + rr * 8;
                int b = p >> 9, t = p & 511;
                float2 v;
                v.x = acc[mt][nt][rr * 2 + 0] + b0;
                v.y = acc[mt][nt][rr * 2 + 1] + b1;
                *(float2*)(Out + ((b * N_HEADS + h) * SEQ + t) * HEAD_DIM + d) = v;
            }
        }
    }
}

// ---------------------------------------------------------------------------
// Kernel 2: fused masked attention via tf32 MMA, online softmax in registers.
// One block per (b, h, 128-query tile). Each warp owns 16 q-rows x 128 keys,
// so S -> P -> PV stays within the warp (P moved C-frag->A-frag by shuffles).
// grid: (SEQ/128, N_HEADS, BATCH)  block: 256
// ---------------------------------------------------------------------------
__global__ __launch_bounds__(256)
void attn_kernel(const int* __restrict__ pb)
{
    __shared__ uint32_t Ks[128][36];
    __shared__ uint32_t Vs[128][36];
    __shared__ int pbk_s[128];

    const int b  = blockIdx.z;
    const int h  = blockIdx.y;
    const int q0 = blockIdx.x * 128;
    const int tid = threadIdx.x;
    const int warp = tid >> 5, lane = tid & 31;
    const int group = lane >> 2, tig = lane & 3;
    const float scale = 0.17677669529663687f; // 1/sqrt(32)

    const float* __restrict__ Qg = g_Q + (b * N_HEADS + h) * SEQ * HEAD_DIM;
    const float* __restrict__ Kg = g_K + (b * N_HEADS + h) * SEQ * HEAD_DIM;
    const float* __restrict__ Vg = g_V + (b * N_HEADS + h) * SEQ * HEAD_DIM;

    const int qrow = q0 + warp * 16;

    // Q A-fragments, held in registers for the whole kernel
    uint32_t aq[4][4];
#pragma unroll
    for (int ks = 0; ks < 4; ks++) {
        aq[ks][0] = f2tf32(Qg[(qrow + group) * 32 + ks * 8 + tig]);
        aq[ks][1] = f2tf32(Qg[(qrow + group + 8) * 32 + ks * 8 + tig]);
        aq[ks][2] = f2tf32(Qg[(qrow + group) * 32 + ks * 8 + tig + 4]);
        aq[ks][3] = f2tf32(Qg[(qrow + group + 8) * 32 + ks * 8 + tig + 4]);
    }
    const int pbq_lo = pb[b * SEQ + qrow + group];
    const int pbq_hi = pb[b * SEQ + qrow + group + 8];

    float m_lo = -1e30f, m_hi = -1e30f, l_lo = 0.f, l_hi = 0.f;
    float o[4][4] = {};

    for (int kt = 0; kt < SEQ; kt += 128) {
        __syncthreads();
        // stage K, V tiles (128 x 32 each)
#pragma unroll
        for (int i = 0; i < 4; i++) {
            int quad = tid + 256 * i;
            int r = quad >> 3, c = (quad & 7) * 4;
            float4 vk = *(const float4*)(Kg + (kt + r) * 32 + c);
            float4 vv = *(const float4*)(Vg + (kt + r) * 32 + c);
            Ks[r][c + 0] = f2tf32(vk.x); Ks[r][c + 1] = f2tf32(vk.y);
            Ks[r][c + 2] = f2tf32(vk.z); Ks[r][c + 3] = f2tf32(vk.w);
            Vs[r][c + 0] = f2tf32(vv.x); Vs[r][c + 1] = f2tf32(vv.y);
            Vs[r][c + 2] = f2tf32(vv.z); Vs[r][c + 3] = f2tf32(vv.w);
        }
        if (tid < 128) pbk_s[tid] = pb[b * SEQ + kt + tid];
        __syncthreads();

        // ---- S = Q K^T  (warp tile 16 x 128) ----
        float sc[16][4];
#pragma unroll
        for (int nt = 0; nt < 16; nt++) { sc[nt][0] = sc[nt][1] = sc[nt][2] = sc[nt][3] = 0.f; }
#pragma unroll
        for (int ks = 0; ks < 4; ks++) {
#pragma unroll
            for (int nt = 0; nt < 16; nt++) {
                int n = nt * 8 + group;
                uint32_t b0 = Ks[n][ks * 8 + tig];
                uint32_t b1 = Ks[n][ks * 8 + tig + 4];
                mma_tf32(sc[nt][0], sc[nt][1], sc[nt][2], sc[nt][3],
                         aq[ks][0], aq[ks][1], aq[ks][2], aq[ks][3], b0, b1);
            }
        }

        // ---- scale + mask, row-max ----
        float mx_lo = -1e30f, mx_hi = -1e30f;
#pragma unroll
        for (int nt = 0; nt < 16; nt++) {
            int col = nt * 8 + 2 * tig;
            int pk0 = pbk_s[col], pk1 = pbk_s[col + 1];
            float v0 = (pbq_lo == pk0) ? -1e9f : sc[nt][0] * scale;
            float v1 = (pbq_lo == pk1) ? -1e9f : sc[nt][1] * scale;
            float v2 = (pbq_hi == pk0) ? -1e9f : sc[nt][2] * scale;
            float v3 = (pbq_hi == pk1) ? -1e9f : sc[nt][3] * scale;
            sc[nt][0] = v0; sc[nt][1] = v1; sc[nt][2] = v2; sc[nt][3] = v3;
            mx_lo = fmaxf(mx_lo, fmaxf(v0, v1));
            mx_hi = fmaxf(mx_hi, fmaxf(v2, v3));
        }
        mx_lo = fmaxf(mx_lo, __shfl_xor_sync(0xffffffffu, mx_lo, 1));
        mx_lo = fmaxf(mx_lo, __shfl_xor_sync(0xffffffffu, mx_lo, 2));
        mx_hi = fmaxf(mx_hi, __shfl_xor_sync(0xffffffffu, mx_hi, 1));
        mx_hi = fmaxf(mx_hi, __shfl_xor_sync(0xffffffffu, mx_hi, 2));

        float mnew_lo = fmaxf(m_lo, mx_lo);
        float mnew_hi = fmaxf(m_hi, mx_hi);
        float al_lo = __expf(m_lo - mnew_lo);
        float al_hi = __expf(m_hi - mnew_hi);
        m_lo = mnew_lo; m_hi = mnew_hi;

        // ---- exp + row sum ----
        float sum_lo = 0.f, sum_hi = 0.f;
#pragma unroll
        for (int nt = 0; nt < 16; nt++) {
            float p0 = __expf(sc[nt][0] - mnew_lo);
            float p1 = __expf(sc[nt][1] - mnew_lo);
            float p2 = __expf(sc[nt][2] - mnew_hi);
            float p3 = __expf(sc[nt][3] - mnew_hi);
            sc[nt][0] = p0; sc[nt][1] = p1; sc[nt][2] = p2; sc[nt][3] = p3;
            sum_lo += p0 + p1;
            sum_hi += p2 + p3;
        }
        sum_lo += __shfl_xor_sync(0xffffffffu, sum_lo, 1);
        sum_lo += __shfl_xor_sync(0xffffffffu, sum_lo, 2);
        sum_hi += __shfl_xor_sync(0xffffffffu, sum_hi, 1);
        sum_hi += __shfl_xor_sync(0xffffffffu, sum_hi, 2);
        l_lo = l_lo * al_lo + sum_lo;
        l_hi = l_hi * al_hi + sum_hi;

        // rescale O accumulators
#pragma unroll
        for (int nt = 0; nt < 4; nt++) {
            o[nt][0] *= al_lo; o[nt][1] *= al_lo;
            o[nt][2] *= al_hi; o[nt][3] *= al_hi;
        }

        // ---- O += P V : build P A-frags via intra-quad shuffles ----
        const int qbase = lane & 28;
        const int s1 = qbase | (tig >> 1);
        const int s2 = s1 + 2;
        const bool odd = tig & 1;
#pragma unroll
        for (int ks = 0; ks < 16; ks++) {
            float p0 = sc[ks][0], p1 = sc[ks][1], p2 = sc[ks][2], p3 = sc[ks][3];
            float u0 = __shfl_sync(0xffffffffu, p0, s1);
            float u1 = __shfl_sync(0xffffffffu, p1, s1);
            float w0 = __shfl_sync(0xffffffffu, p2, s1);
            float w1 = __shfl_sync(0xffffffffu, p3, s1);
            float x0 = __shfl_sync(0xffffffffu, p0, s2);
            float x1 = __shfl_sync(0xffffffffu, p1, s2);
            float y0 = __shfl_sync(0xffffffffu, p2, s2);
            float y1 = __shfl_sync(0xffffffffu, p3, s2);
            uint32_t a0 = f2tf32(odd ? u1 : u0);
            uint32_t a1 = f2tf32(odd ? w1 : w0);
            uint32_t a2 = f2tf32(odd ? x1 : x0);
            uint32_t a3 = f2tf32(odd ? y1 : y0);
#pragma unroll
            for (int nt = 0; nt < 4; nt++) {
                uint32_t b0 = Vs[ks * 8 + tig][nt * 8 + group];
                uint32_t b1 = Vs[ks * 8 + tig + 4][nt * 8 + group];
                mma_tf32(o[nt][0], o[nt][1], o[nt][2], o[nt][3], a0, a1, a2, a3, b0, b1);
            }
        }
    }

    // ---- normalize and write y[token][channel] ----
    float inv_lo = 1.f / l_lo;
    float inv_hi = 1.f / l_hi;
    int tok_lo = b * SEQ + qrow + group;
    int tok_hi = tok_lo + 8;
#pragma unroll
    for (int nt = 0; nt < 4; nt++) {
        int c = h * HEAD_DIM + nt * 8 + 2 * tig;
        float2 vlo; vlo.x = o[nt][0] * inv_lo; vlo.y = o[nt][1] * inv_lo;
        float2 vhi; vhi.x = o[nt][2] * inv_hi; vhi.y = o[nt][3] * inv_hi;
        *(float2*)(g_Y + tok_lo * D_MODEL + c) = vlo;
        *(float2*)(g_Y + tok_hi * D_MODEL + c) = vhi;
    }
}

// ---------------------------------------------------------------------------
// Kernel 3: output projection fused with inverse-index gather (tf32 MMA).
// out[n][c] = sum_k Y[inv[n]][k] * Wp[c][k] + bp[c]
// grid: (N_TOTAL/128, 4)  block: 256
// ---------------------------------------------------------------------------
__global__ __launch_bounds__(256)
void proj_kernel(const float* __restrict__ Wp, const float* __restrict__ bp,
                 const int* __restrict__ inv, float* __restrict__ out)
{
    __shared__ uint32_t As[128][36];
    __shared__ uint32_t Bs[64][36];
    __shared__ int rowIdx[128];

    const int m0 = blockIdx.x * 128;
    const int n0 = blockIdx.y * 64;
    const int tid = threadIdx.x;
    const int warp = tid >> 5, lane = tid & 31;
    const int wm = warp >> 1, wn = warp & 1;
    const int group = lane >> 2, tig = lane & 3;

    if (tid < 128) rowIdx[tid] = inv[m0 + tid];
    __syncthreads();

    float acc[2][4][4] = {};

    for (int kk = 0; kk < D_MODEL; kk += 32) {
#pragma unroll
        for (int i = 0; i < 4; i++) {
            int quad = tid + 256 * i;
            int r = quad >> 3, c = (quad & 7) * 4;
            const float4 v = *(const float4*)(g_Y + rowIdx[r] * D_MODEL + kk + c);
            As[r][c + 0] = f2tf32(v.x);
            As[r][c + 1] = f2tf32(v.y);
            As[r][c + 2] = f2tf32(v.z);
            As[r][c + 3] = f2tf32(v.w);
        }
#pragma unroll
        for (int i = 0; i < 2; i++) {
            int quad = tid + 256 * i;
            int r = quad >> 3, c = (quad & 7) * 4;
            const float4 v = *(const float4*)(Wp + (n0 + r) * D_MODEL + kk + c);
            Bs[r][c + 0] = f2tf32(v.x);
            Bs[r][c + 1] = f2tf32(v.y);
            Bs[r][c + 2] = f2tf32(v.z);
            Bs[r][c + 3] = f2tf32(v.w);
        }
        __syncthreads();

#pragma unroll
        for (int ks = 0; ks < 4; ks++) {
            uint32_t afr[2][4];
#pragma unroll
            for (int mt = 0; mt < 2; mt++) {
                int r = wm * 32 + mt * 16 + group;
                afr[mt][0] = As[r][ks * 8 + tig];
                afr[mt][1] = As[r + 8][ks * 8 + tig];
                afr[mt][2] = As[r][ks * 8 + tig + 4];
                afr[mt][3] = As[r + 8][ks * 8 + tig + 4];
            }
#pragma unroll
            for (int nt = 0; nt < 4; nt++) {
                int n = wn * 32 + nt * 8 + group;
                uint32_t b0 = Bs[n][ks * 8 + tig];
                uint32_t b1 = Bs[n][ks * 8 + tig + 4];
#pragma unroll
                for (int mt = 0; mt < 2; mt++)
                    mma_tf32(acc[mt][nt][0], acc[mt][nt][1], acc[mt][nt][2], acc[mt][nt][3],
                             afr[mt][0], afr[mt][1], afr[mt][2], afr[mt][3], b0, b1);
            }
        }
        __syncthreads();
    }

#pragma unroll
    for (int mt = 0; mt < 2; mt++) {
#pragma unroll
        for (int nt = 0; nt < 4; nt++) {
            int c = n0 + wn * 32 + nt * 8 + 2 * tig;
            float b0 = bp[c], b1 = bp[c + 1];
#pragma unroll
            for (int rr = 0; rr < 2; rr++) {
                int n = m0 + wm * 32 + mt * 16 + group + rr * 8;
                float2 v;
                v.x = acc[mt][nt][rr * 2 + 0] + b0;
                v.y = acc[mt][nt][rr * 2 + 1] + b1;
                *(float2*)(out + n * D_MODEL + c) = v;
            }
        }
    }
}

// ---------------------------------------------------------------------------
extern "C" void kernel_launch(void* const* d_in, const int* in_sizes, int n_in,
                              void* d_out, int out_size)
{
    const float* x  = (const float*)d_in[0];
    const float* Wq = (const float*)d_in[1];
    const float* bq = (const float*)d_in[2];
    const float* Wk = (const float*)d_in[3];
    const float* bk = (const float*)d_in[4];
    const float* Wv = (const float*)d_in[5];
    const float* bv = (const float*)d_in[6];
    const float* Wp = (const float*)d_in[7];
    const float* bp = (const float*)d_in[8];
    const int* idx  = (const int*)d_in[9];
    const int* pb   = (const int*)d_in[10];
    const int* inv  = (const int*)d_in[11];
    float* out = (float*)d_out;

    dim3 g1(NP / 128, D_MODEL / 64, 3);
    qkv_kernel<<<g1, 256>>>(x, idx, Wq, bq, Wk, bk, Wv, bv);

    dim3 g2(SEQ / 128, N_HEADS, BATCH);
    attn_kernel<<<g2, 256>>>(pb);

    dim3 g3(N_TOTAL / 128, D_MODEL / 64);
    proj_kernel<<<g3, 256>>>(Wp, bp, inv, out);
}